// round 16
// baseline (speedup 1.0000x reference)
#include <cuda_runtime.h>
#include <cuda_fp16.h>
#include <cstdint>

#define NN   1024
#define TT   36
#define EMB  64
#define NH   4
#define HD   16
#define QSCALE 0.18033688f   // 0.125 * log2(e)

typedef unsigned long long ull;

#define EX2(d,a) asm("ex2.approx.ftz.f32 %0, %1;" : "=f"(d) : "f"(a))
#define TF32(u,f) asm("cvt.rna.tf32.f32 %0, %1;" : "=r"(u) : "f"(f))
// first fp32 operand -> HIGH half, second -> LOW half
#define F16X2(r,hi,lo) asm("cvt.rn.f16x2.f32 %0, %1, %2;" : "=r"(r) : "f"(hi), "f"(lo))

#define MMA_TF32(d, a, b0, b1) \
    asm volatile("mma.sync.aligned.m16n8k8.row.col.f32.tf32.tf32.f32 " \
        "{%0,%1,%2,%3}, {%4,%5,%6,%7}, {%8,%9}, {%0,%1,%2,%3};" \
        : "+f"((d)[0]), "+f"((d)[1]), "+f"((d)[2]), "+f"((d)[3]) \
        : "r"((a)[0]), "r"((a)[1]), "r"((a)[2]), "r"((a)[3]), "r"(b0), "r"(b1))

#define MMA_F16(d, a, b0, b1) \
    asm volatile("mma.sync.aligned.m16n8k16.row.col.f32.f16.f16.f32 " \
        "{%0,%1,%2,%3}, {%4,%5,%6,%7}, {%8,%9}, {%0,%1,%2,%3};" \
        : "+f"((d)[0]), "+f"((d)[1]), "+f"((d)[2]), "+f"((d)[3]) \
        : "r"((a)[0]), "r"((a)[1]), "r"((a)[2]), "r"((a)[3]), "r"(b0), "r"(b1))

#define LDMX4(r, addr) \
    asm volatile("ldmatrix.sync.aligned.m8n8.x4.shared.b16 {%0,%1,%2,%3}, [%4];" \
        : "=r"((r)[0]), "=r"((r)[1]), "=r"((r)[2]), "=r"((r)[3]) : "r"(addr))

__device__ __forceinline__ uint32_t smem_u32(const void* p) {
    uint32_t a;
    asm("{ .reg .u64 t; cvta.to.shared.u64 t, %1; cvt.u32.u64 %0, t; }" : "=r"(a) : "l"(p));
    return a;
}

// SMEM layout (u32 word offsets). Qt/Kt: transposed [16 d][1032 stride] tf32.
// V2h: fp16x2 key-pairs [512 pairs][20 u32 stride] (V hi only — see theory).
#define QT_W   0
#define KT_W   16512
#define V2H_W  33024
#define SMEM_WORDS 43264
#define DYN_SMEM (SMEM_WORDS * 4)

__device__ float g_ctx[(size_t)NN * TT * EMB];

// ---------------------------------------------------------------------------
// Fused QKV projection + node attention (tf32 QK^T, fp16 PV, V hi-only).
// One CTA per (t, h); 8 warps (R8 shape: 2 warps/SMSP, ~150 regs of ILP);
// q-tiles processed in PAIRS sharing K/V fragment loads.
// ---------------------------------------------------------------------------
__global__ __launch_bounds__(256, 1)
void attn_kernel(const float* __restrict__ values,
                 const float* __restrict__ keys,
                 const float* __restrict__ query,
                 const float* __restrict__ Wv,
                 const float* __restrict__ Wk,
                 const float* __restrict__ Wq)
{
    extern __shared__ uint32_t smw[];
    __shared__ float Wks[HD * HD], Wvs[HD * HD], Wqs[HD * HD];

    const int tid = threadIdx.x;
    const int tt  = blockIdx.x / NH;
    const int h   = blockIdx.x % NH;

    if (tid < HD * HD) { Wks[tid] = Wk[tid]; Wvs[tid] = Wv[tid]; Wqs[tid] = Wq[tid]; }
    __syncthreads();

    // ---- prologue: project Q,K (tf32, transposed) and V (fp16 pairs) ----
    #pragma unroll
    for (int r = 0; r < 4; r++) {
        const int n = tid + r * 256;
        const size_t src = ((size_t)n * TT + tt) * EMB + h * HD;
        float kin[HD], vin[HD], qin[HD];
        #pragma unroll
        for (int i = 0; i < 4; i++) {
            float4 a = *(const float4*)(keys   + src + i * 4);
            kin[i*4+0]=a.x; kin[i*4+1]=a.y; kin[i*4+2]=a.z; kin[i*4+3]=a.w;
            float4 b = *(const float4*)(values + src + i * 4);
            vin[i*4+0]=b.x; vin[i*4+1]=b.y; vin[i*4+2]=b.z; vin[i*4+3]=b.w;
            float4 c = *(const float4*)(query  + src + i * 4);
            qin[i*4+0]=c.x; qin[i*4+1]=c.y; qin[i*4+2]=c.z; qin[i*4+3]=c.w;
        }
        #pragma unroll
        for (int e = 0; e < HD; e++) {
            float sk = 0.f, sv = 0.f, sq = 0.f;
            #pragma unroll
            for (int d = 0; d < HD; d++) {
                sk = fmaf(kin[d], Wks[e * HD + d], sk);
                sv = fmaf(vin[d], Wvs[e * HD + d], sv);
                sq = fmaf(qin[d], Wqs[e * HD + d], sq);
            }
            uint32_t kb, qb;
            TF32(kb, sk);
            TF32(qb, sq * QSCALE);
            smw[KT_W + e * 1032 + n] = kb;
            smw[QT_W + e * 1032 + n] = qb;
            const uint32_t woff = (uint32_t)(n >> 1) * 20 + e;
            ((__half*)(smw + V2H_W + woff))[n & 1] = __float2half_rn(sv);
        }
    }
    __syncthreads();

    // ---- mainloop: 4 pairs of q-tiles per warp ----
    const int lane = tid & 31, w = tid >> 5;
    const int g = lane >> 2, t = lane & 3;

    const uint32_t* Qt  = smw + QT_W;
    const uint32_t* Kt  = smw + KT_W;
    const uint32_t* V2h = smw + V2H_W;

    for (int i = 0; i < 4; i++) {
        const int q0a = (w * 8 + 2 * i) * 16;

        uint32_t qaA[2][4], qaB[2][4];
        #pragma unroll
        for (int ks = 0; ks < 2; ks++) {
            const uint32_t* qc = Qt + (ks * 8 + t) * 1032 + q0a;
            qaA[ks][0] = qc[g];
            qaA[ks][1] = qc[g + 8];
            qaA[ks][2] = qc[4 * 1032 + g];
            qaA[ks][3] = qc[4 * 1032 + g + 8];
            qaB[ks][0] = qc[16 + g];
            qaB[ks][1] = qc[16 + g + 8];
            qaB[ks][2] = qc[4 * 1032 + 16 + g];
            qaB[ks][3] = qc[4 * 1032 + 16 + g + 8];
        }

        float oA0[4] = {0,0,0,0}, oA1[4] = {0,0,0,0};
        float oB0[4] = {0,0,0,0}, oB1[4] = {0,0,0,0};
        float lsA0 = 0.f, lsA1 = 0.f, lsB0 = 0.f, lsB1 = 0.f;

        for (int kc = 0; kc < 64; kc++) {
            const int k0 = kc * 16;

            // ---- QK^T for both tiles (shared K frags) ----
            float dA0[4] = {0,0,0,0}, dA1[4] = {0,0,0,0};
            float dB0[4] = {0,0,0,0}, dB1[4] = {0,0,0,0};
            #pragma unroll
            for (int ks = 0; ks < 2; ks++) {
                const uint32_t* kcp = Kt + (ks * 8 + t) * 1032 + k0;
                uint32_t b0 = kcp[g],     b1 = kcp[4 * 1032 + g];
                uint32_t c0 = kcp[8 + g], c1 = kcp[4 * 1032 + 8 + g];
                MMA_TF32(dA0, qaA[ks], b0, b1);
                MMA_TF32(dA1, qaA[ks], c0, c1);
                MMA_TF32(dB0, qaB[ks], b0, b1);
                MMA_TF32(dB1, qaB[ks], c0, c1);
            }

            // ---- exp ----
            float pA0[4], pA1[4], pB0[4], pB1[4];
            #pragma unroll
            for (int j = 0; j < 4; j++) {
                EX2(pA0[j], dA0[j]); EX2(pA1[j], dA1[j]);
                EX2(pB0[j], dB0[j]); EX2(pB1[j], dB1[j]);
            }
            lsA0 += (pA0[0] + pA0[1]) + (pA1[0] + pA1[1]);
            lsA1 += (pA0[2] + pA0[3]) + (pA1[2] + pA1[3]);
            lsB0 += (pB0[0] + pB0[1]) + (pB1[0] + pB1[1]);
            lsB1 += (pB0[2] + pB0[3]) + (pB1[2] + pB1[3]);

            uint32_t paA[4], paB[4];
            F16X2(paA[0], pA0[1], pA0[0]);
            F16X2(paA[1], pA0[3], pA0[2]);
            F16X2(paA[2], pA1[1], pA1[0]);
            F16X2(paA[3], pA1[3], pA1[2]);
            F16X2(paB[0], pB0[1], pB0[0]);
            F16X2(paB[1], pB0[3], pB0[2]);
            F16X2(paB[2], pB1[1], pB1[0]);
            F16X2(paB[3], pB1[3], pB1[2]);

            // ---- PV (shared V frags, hi pass only) ----
            const uint32_t* vh = V2h + (kc * 8 + t) * 20;
            uint32_t bh0 = vh[g],     bh1 = vh[4 * 20 + g];
            uint32_t bh2 = vh[8 + g], bh3 = vh[4 * 20 + 8 + g];
            MMA_F16(oA0, paA, bh0, bh1);
            MMA_F16(oA1, paA, bh2, bh3);
            MMA_F16(oB0, paB, bh0, bh1);
            MMA_F16(oB1, paB, bh2, bh3);
        }

        // ---- reduce + store both tiles ----
        #pragma unroll
        for (int tb = 0; tb < 2; tb++) {
            float ls0 = tb ? lsB0 : lsA0;
            float ls1 = tb ? lsB1 : lsA1;
            float* o0 = tb ? oB0 : oA0;
            float* o1 = tb ? oB1 : oA1;
            ls0 += __shfl_xor_sync(0xffffffffu, ls0, 1);
            ls0 += __shfl_xor_sync(0xffffffffu, ls0, 2);
            ls1 += __shfl_xor_sync(0xffffffffu, ls1, 1);
            ls1 += __shfl_xor_sync(0xffffffffu, ls1, 2);
            const float inv0 = 1.f / ls0;
            const float inv1 = 1.f / ls1;
            const int row0 = q0a + tb * 16 + g;
            float* p = g_ctx + ((size_t)row0 * TT + tt) * EMB + h * HD;
            float2 u;
            u.x = o0[0] * inv0; u.y = o0[1] * inv0; *(float2*)(p + 2 * t)     = u;
            u.x = o1[0] * inv0; u.y = o1[1] * inv0; *(float2*)(p + 8 + 2 * t) = u;
            float* q = g_ctx + ((size_t)(row0 + 8) * TT + tt) * EMB + h * HD;
            u.x = o0[2] * inv1; u.y = o0[3] * inv1; *(float2*)(q + 2 * t)     = u;
            u.x = o1[2] * inv1; u.y = o1[3] * inv1; *(float2*)(q + 8 + 2 * t) = u;
        }
    }
}

// ---------------------------------------------------------------------------
// Kernel 2: output projection via mma.sync, fp16 hi/lo 3-pass (R8 shape,
// 256 threads) with ctx LDG.128s hoisted ahead of the Wo pack.
// ---------------------------------------------------------------------------
__global__ __launch_bounds__(256)
void oproj_kernel(const float* __restrict__ Wo,
                  const float* __restrict__ bo,
                  float* __restrict__ out)
{
    __shared__ uint32_t Wh2[EMB][33], Wl2[EMB][33];
    __shared__ float bos[EMB];
    __shared__ __align__(16) __half stageH[8][16][72];
    __shared__ __align__(16) __half stageL[8][16][72];

    const int tid = threadIdx.x;
    const int lane = tid & 31, w = tid >> 5;
    const int g = lane >> 2, t = lane & 3;
    const int rowbase = (blockIdx.x * 8 + w) * 16;

    // ---- issue ctx loads FIRST (independent of smem) ----
    float4 v[8];
    {
        const float4* cp = (const float4*)(g_ctx + (size_t)rowbase * EMB);
        #pragma unroll
        for (int k = 0; k < 8; k++) v[k] = cp[lane + k * 32];
    }

    // ---- pack Wo into fp16x2 hi/lo B-operand pairs (overlaps ctx LDG) ----
    for (int idx = tid; idx < EMB * 32; idx += 256) {
        const int e = idx >> 5, j = idx & 31;
        float w0 = Wo[e * EMB + 2 * j], w1 = Wo[e * EMB + 2 * j + 1];
        __half h0 = __float2half_rn(w0), h1 = __float2half_rn(w1);
        __half l0 = __float2half_rn(w0 - __half2float(h0));
        __half l1 = __float2half_rn(w1 - __half2float(h1));
        Wh2[e][j] = ((uint32_t)__half_as_ushort(h1) << 16) | __half_as_ushort(h0);
        Wl2[e][j] = ((uint32_t)__half_as_ushort(l1) << 16) | __half_as_ushort(l0);
    }
    if (tid < EMB) bos[tid] = bo[tid];

    // ---- stage this warp's 16 ctx rows as fp16 hi/lo ----
    #pragma unroll
    for (int k = 0; k < 8; k++) {
        const int f = lane + k * 32;
        const int row = f >> 4, c4 = f & 15;
        float xs[4] = {v[k].x, v[k].y, v[k].z, v[k].w};
        uint32_t hw[2], lw[2];
        #pragma unroll
        for (int j = 0; j < 2; j++) {
            __half h0 = __float2half_rn(xs[2*j]),   h1 = __float2half_rn(xs[2*j+1]);
            __half l0 = __float2half_rn(xs[2*j]   - __half2float(h0));
            __half l1 = __float2half_rn(xs[2*j+1] - __half2float(h1));
            hw[j] = ((uint32_t)__half_as_ushort(h1) << 16) | __half_as_ushort(h0);
            lw[j] = ((uint32_t)__half_as_ushort(l1) << 16) | __half_as_ushort(l0);
        }
        uint32_t* ph = (uint32_t*)&stageH[w][row][c4 * 4];
        uint32_t* pl = (uint32_t*)&stageL[w][row][c4 * 4];
        ph[0] = hw[0]; ph[1] = hw[1];
        pl[0] = lw[0]; pl[1] = lw[1];
    }
    __syncthreads();   // Wo pack (block-wide); own-warp staging also done

    // ---- A-fragments via ldmatrix.x4 (4 k-steps) ----
    const int m = lane >> 3, i8 = lane & 7;
    const int arow = (m & 1) * 8 + i8;
    const int acol = (m >> 1) * 8;
    uint32_t ah[4][4], al[4][4];
    #pragma unroll
    for (int ks = 0; ks < 4; ks++) {
        LDMX4(ah[ks], smem_u32(&stageH[w][arow][ks * 16 + acol]));
        LDMX4(al[ks], smem_u32(&stageL[w][arow][ks * 16 + acol]));
    }

    // ---- 8 e-tiles of n8; 3-pass hi/lo mma; bias in D init ----
    #pragma unroll
    for (int et = 0; et < 8; et++) {
        const float b0v = bos[et * 8 + 2 * t];
        const float b1v = bos[et * 8 + 2 * t + 1];
        float d[4] = {b0v, b1v, b0v, b1v};
        #pragma unroll
        for (int ks = 0; ks < 4; ks++) {
            const int e = et * 8 + g;
            uint32_t bh0 = Wh2[e][ks * 8 + t], bh1 = Wh2[e][ks * 8 + t + 4];
            uint32_t bl0 = Wl2[e][ks * 8 + t], bl1 = Wl2[e][ks * 8 + t + 4];
            MMA_F16(d, ah[ks], bh0, bh1);
            MMA_F16(d, ah[ks], bl0, bl1);
            MMA_F16(d, al[ks], bh0, bh1);
        }
        float2 u;
        u.x = d[0]; u.y = d[1];
        *(float2*)(out + (size_t)(rowbase + g) * EMB + et * 8 + 2 * t) = u;
        u.x = d[2]; u.y = d[3];
        *(float2*)(out + (size_t)(rowbase + g + 8) * EMB + et * 8 + 2 * t) = u;
    }
}

// ---------------------------------------------------------------------------
extern "C" void kernel_launch(void* const* d_in, const int* in_sizes, int n_in,
                              void* d_out, int out_size)
{
    const float* values = (const float*)d_in[0];
    const float* keys   = (const float*)d_in[1];
    const float* query  = (const float*)d_in[2];
    const float* Wv     = (const float*)d_in[3];
    const float* Wk     = (const float*)d_in[4];
    const float* Wq     = (const float*)d_in[5];
    const float* Wo     = (const float*)d_in[6];
    const float* bo     = (const float*)d_in[7];
    float* out = (float*)d_out;

    cudaFuncSetAttribute(attn_kernel,
                         cudaFuncAttributeMaxDynamicSharedMemorySize, DYN_SMEM);

    attn_kernel<<<TT * NH, 256, DYN_SMEM>>>(values, keys, query, Wv, Wk, Wq);
    oproj_kernel<<<(NN * TT) / 128, 256>>>(Wo, bo, out);
}

// round 17
// speedup vs baseline: 1.0133x; 1.0133x over previous
#include <cuda_runtime.h>
#include <cuda_fp16.h>
#include <cstdint>

#define NN   1024
#define TT   36
#define EMB  64
#define NH   4
#define HD   16
#define QSCALE 0.18033688f   // 0.125 * log2(e)

typedef unsigned long long ull;

#define EX2(d,a) asm("ex2.approx.ftz.f32 %0, %1;" : "=f"(d) : "f"(a))
#define TF32(u,f) asm("cvt.rna.tf32.f32 %0, %1;" : "=r"(u) : "f"(f))
// first fp32 operand -> HIGH half, second -> LOW half
#define F16X2(r,hi,lo) asm("cvt.rn.f16x2.f32 %0, %1, %2;" : "=r"(r) : "f"(hi), "f"(lo))

#define MMA_TF32(d, a, b0, b1) \
    asm volatile("mma.sync.aligned.m16n8k8.row.col.f32.tf32.tf32.f32 " \
        "{%0,%1,%2,%3}, {%4,%5,%6,%7}, {%8,%9}, {%0,%1,%2,%3};" \
        : "+f"((d)[0]), "+f"((d)[1]), "+f"((d)[2]), "+f"((d)[3]) \
        : "r"((a)[0]), "r"((a)[1]), "r"((a)[2]), "r"((a)[3]), "r"(b0), "r"(b1))

#define MMA_F16(d, a, b0, b1) \
    asm volatile("mma.sync.aligned.m16n8k16.row.col.f32.f16.f16.f32 " \
        "{%0,%1,%2,%3}, {%4,%5,%6,%7}, {%8,%9}, {%0,%1,%2,%3};" \
        : "+f"((d)[0]), "+f"((d)[1]), "+f"((d)[2]), "+f"((d)[3]) \
        : "r"((a)[0]), "r"((a)[1]), "r"((a)[2]), "r"((a)[3]), "r"(b0), "r"(b1))

#define LDMX4(r, addr) \
    asm volatile("ldmatrix.sync.aligned.m8n8.x4.shared.b16 {%0,%1,%2,%3}, [%4];" \
        : "=r"((r)[0]), "=r"((r)[1]), "=r"((r)[2]), "=r"((r)[3]) : "r"(addr))

__device__ __forceinline__ uint32_t smem_u32(const void* p) {
    uint32_t a;
    asm("{ .reg .u64 t; cvta.to.shared.u64 t, %1; cvt.u32.u64 %0, t; }" : "=r"(a) : "l"(p));
    return a;
}

// SMEM layout (u32 word offsets). Qt/Kt: transposed [16 d][1032 stride] tf32.
// V2h: fp16x2 key-pairs [512 pairs][20 u32 stride] (V hi only — see theory).
#define QT_W   0
#define KT_W   16512
#define V2H_W  33024
#define SMEM_WORDS 43264
#define DYN_SMEM (SMEM_WORDS * 4)

__device__ float g_ctx[(size_t)NN * TT * EMB];

// ---------------------------------------------------------------------------
// Fused QKV projection + node attention (tf32 QK^T, fp16 PV, V hi-only).
// One CTA per (t, h); 8 warps (R8 shape: 2 warps/SMSP, ~150 regs of ILP);
// q-tiles processed in PAIRS sharing K/V fragment loads.
// ---------------------------------------------------------------------------
__global__ __launch_bounds__(256, 1)
void attn_kernel(const float* __restrict__ values,
                 const float* __restrict__ keys,
                 const float* __restrict__ query,
                 const float* __restrict__ Wv,
                 const float* __restrict__ Wk,
                 const float* __restrict__ Wq)
{
    extern __shared__ uint32_t smw[];
    __shared__ float Wks[HD * HD], Wvs[HD * HD], Wqs[HD * HD];

    const int tid = threadIdx.x;
    const int tt  = blockIdx.x / NH;
    const int h   = blockIdx.x % NH;

    if (tid < HD * HD) { Wks[tid] = Wk[tid]; Wvs[tid] = Wv[tid]; Wqs[tid] = Wq[tid]; }
    __syncthreads();

    // ---- prologue: project Q,K (tf32, transposed) and V (fp16 pairs) ----
    #pragma unroll
    for (int r = 0; r < 4; r++) {
        const int n = tid + r * 256;
        const size_t src = ((size_t)n * TT + tt) * EMB + h * HD;
        float kin[HD], vin[HD], qin[HD];
        #pragma unroll
        for (int i = 0; i < 4; i++) {
            float4 a = *(const float4*)(keys   + src + i * 4);
            kin[i*4+0]=a.x; kin[i*4+1]=a.y; kin[i*4+2]=a.z; kin[i*4+3]=a.w;
            float4 b = *(const float4*)(values + src + i * 4);
            vin[i*4+0]=b.x; vin[i*4+1]=b.y; vin[i*4+2]=b.z; vin[i*4+3]=b.w;
            float4 c = *(const float4*)(query  + src + i * 4);
            qin[i*4+0]=c.x; qin[i*4+1]=c.y; qin[i*4+2]=c.z; qin[i*4+3]=c.w;
        }
        #pragma unroll
        for (int e = 0; e < HD; e++) {
            float sk = 0.f, sv = 0.f, sq = 0.f;
            #pragma unroll
            for (int d = 0; d < HD; d++) {
                sk = fmaf(kin[d], Wks[e * HD + d], sk);
                sv = fmaf(vin[d], Wvs[e * HD + d], sv);
                sq = fmaf(qin[d], Wqs[e * HD + d], sq);
            }
            uint32_t kb, qb;
            TF32(kb, sk);
            TF32(qb, sq * QSCALE);
            smw[KT_W + e * 1032 + n] = kb;
            smw[QT_W + e * 1032 + n] = qb;
            const uint32_t woff = (uint32_t)(n >> 1) * 20 + e;
            ((__half*)(smw + V2H_W + woff))[n & 1] = __float2half_rn(sv);
        }
    }
    __syncthreads();

    // ---- mainloop: 4 pairs of q-tiles per warp ----
    const int lane = tid & 31, w = tid >> 5;
    const int g = lane >> 2, t = lane & 3;

    const uint32_t* Qt  = smw + QT_W;
    const uint32_t* Kt  = smw + KT_W;
    const uint32_t* V2h = smw + V2H_W;

    for (int i = 0; i < 4; i++) {
        const int q0a = (w * 8 + 2 * i) * 16;

        uint32_t qaA[2][4], qaB[2][4];
        #pragma unroll
        for (int ks = 0; ks < 2; ks++) {
            const uint32_t* qc = Qt + (ks * 8 + t) * 1032 + q0a;
            qaA[ks][0] = qc[g];
            qaA[ks][1] = qc[g + 8];
            qaA[ks][2] = qc[4 * 1032 + g];
            qaA[ks][3] = qc[4 * 1032 + g + 8];
            qaB[ks][0] = qc[16 + g];
            qaB[ks][1] = qc[16 + g + 8];
            qaB[ks][2] = qc[4 * 1032 + 16 + g];
            qaB[ks][3] = qc[4 * 1032 + 16 + g + 8];
        }

        float oA0[4] = {0,0,0,0}, oA1[4] = {0,0,0,0};
        float oB0[4] = {0,0,0,0}, oB1[4] = {0,0,0,0};
        float lsA0 = 0.f, lsA1 = 0.f, lsB0 = 0.f, lsB1 = 0.f;

        for (int kc = 0; kc < 64; kc++) {
            const int k0 = kc * 16;

            // ---- QK^T for both tiles (shared K frags) ----
            float dA0[4] = {0,0,0,0}, dA1[4] = {0,0,0,0};
            float dB0[4] = {0,0,0,0}, dB1[4] = {0,0,0,0};
            #pragma unroll
            for (int ks = 0; ks < 2; ks++) {
                const uint32_t* kcp = Kt + (ks * 8 + t) * 1032 + k0;
                uint32_t b0 = kcp[g],     b1 = kcp[4 * 1032 + g];
                uint32_t c0 = kcp[8 + g], c1 = kcp[4 * 1032 + 8 + g];
                MMA_TF32(dA0, qaA[ks], b0, b1);
                MMA_TF32(dA1, qaA[ks], c0, c1);
                MMA_TF32(dB0, qaB[ks], b0, b1);
                MMA_TF32(dB1, qaB[ks], c0, c1);
            }

            // ---- exp ----
            float pA0[4], pA1[4], pB0[4], pB1[4];
            #pragma unroll
            for (int j = 0; j < 4; j++) {
                EX2(pA0[j], dA0[j]); EX2(pA1[j], dA1[j]);
                EX2(pB0[j], dB0[j]); EX2(pB1[j], dB1[j]);
            }
            lsA0 += (pA0[0] + pA0[1]) + (pA1[0] + pA1[1]);
            lsA1 += (pA0[2] + pA0[3]) + (pA1[2] + pA1[3]);
            lsB0 += (pB0[0] + pB0[1]) + (pB1[0] + pB1[1]);
            lsB1 += (pB0[2] + pB0[3]) + (pB1[2] + pB1[3]);

            uint32_t paA[4], paB[4];
            F16X2(paA[0], pA0[1], pA0[0]);
            F16X2(paA[1], pA0[3], pA0[2]);
            F16X2(paA[2], pA1[1], pA1[0]);
            F16X2(paA[3], pA1[3], pA1[2]);
            F16X2(paB[0], pB0[1], pB0[0]);
            F16X2(paB[1], pB0[3], pB0[2]);
            F16X2(paB[2], pB1[1], pB1[0]);
            F16X2(paB[3], pB1[3], pB1[2]);

            // ---- PV (shared V frags, hi pass only) ----
            const uint32_t* vh = V2h + (kc * 8 + t) * 20;
            uint32_t bh0 = vh[g],     bh1 = vh[4 * 20 + g];
            uint32_t bh2 = vh[8 + g], bh3 = vh[4 * 20 + 8 + g];
            MMA_F16(oA0, paA, bh0, bh1);
            MMA_F16(oA1, paA, bh2, bh3);
            MMA_F16(oB0, paB, bh0, bh1);
            MMA_F16(oB1, paB, bh2, bh3);
        }

        // ---- reduce + store both tiles ----
        #pragma unroll
        for (int tb = 0; tb < 2; tb++) {
            float ls0 = tb ? lsB0 : lsA0;
            float ls1 = tb ? lsB1 : lsA1;
            float* o0 = tb ? oB0 : oA0;
            float* o1 = tb ? oB1 : oA1;
            ls0 += __shfl_xor_sync(0xffffffffu, ls0, 1);
            ls0 += __shfl_xor_sync(0xffffffffu, ls0, 2);
            ls1 += __shfl_xor_sync(0xffffffffu, ls1, 1);
            ls1 += __shfl_xor_sync(0xffffffffu, ls1, 2);
            const float inv0 = 1.f / ls0;
            const float inv1 = 1.f / ls1;
            const int row0 = q0a + tb * 16 + g;
            float* p = g_ctx + ((size_t)row0 * TT + tt) * EMB + h * HD;
            float2 u;
            u.x = o0[0] * inv0; u.y = o0[1] * inv0; *(float2*)(p + 2 * t)     = u;
            u.x = o1[0] * inv0; u.y = o1[1] * inv0; *(float2*)(p + 8 + 2 * t) = u;
            float* q = g_ctx + ((size_t)(row0 + 8) * TT + tt) * EMB + h * HD;
            u.x = o0[2] * inv1; u.y = o0[3] * inv1; *(float2*)(q + 2 * t)     = u;
            u.x = o1[2] * inv1; u.y = o1[3] * inv1; *(float2*)(q + 8 + 2 * t) = u;
        }
    }
}

// ---------------------------------------------------------------------------
// Kernel 2: output projection via mma.sync, fp16 hi/lo 3-pass (R8 shape,
// 256 threads) with ctx LDG.128s hoisted ahead of the Wo pack.
// ---------------------------------------------------------------------------
__global__ __launch_bounds__(256)
void oproj_kernel(const float* __restrict__ Wo,
                  const float* __restrict__ bo,
                  float* __restrict__ out)
{
    __shared__ uint32_t Wh2[EMB][33], Wl2[EMB][33];
    __shared__ float bos[EMB];
    __shared__ __align__(16) __half stageH[8][16][72];
    __shared__ __align__(16) __half stageL[8][16][72];

    const int tid = threadIdx.x;
    const int lane = tid & 31, w = tid >> 5;
    const int g = lane >> 2, t = lane & 3;
    const int rowbase = (blockIdx.x * 8 + w) * 16;

    // ---- issue ctx loads FIRST (independent of smem) ----
    float4 v[8];
    {
        const float4* cp = (const float4*)(g_ctx + (size_t)rowbase * EMB);
        #pragma unroll
        for (int k = 0; k < 8; k++) v[k] = cp[lane + k * 32];
    }

    // ---- pack Wo into fp16x2 hi/lo B-operand pairs (overlaps ctx LDG) ----
    for (int idx = tid; idx < EMB * 32; idx += 256) {
        const int e = idx >> 5, j = idx & 31;
        float w0 = Wo[e * EMB + 2 * j], w1 = Wo[e * EMB + 2 * j + 1];
        __half h0 = __float2half_rn(w0), h1 = __float2half_rn(w1);
        __half l0 = __float2half_rn(w0 - __half2float(h0));
        __half l1 = __float2half_rn(w1 - __half2float(h1));
        Wh2[e][j] = ((uint32_t)__half_as_ushort(h1) << 16) | __half_as_ushort(h0);
        Wl2[e][j] = ((uint32_t)__half_as_ushort(l1) << 16) | __half_as_ushort(l0);
    }
    if (tid < EMB) bos[tid] = bo[tid];

    // ---- stage this warp's 16 ctx rows as fp16 hi/lo ----
    #pragma unroll
    for (int k = 0; k < 8; k++) {
        const int f = lane + k * 32;
        const int row = f >> 4, c4 = f & 15;
        float xs[4] = {v[k].x, v[k].y, v[k].z, v[k].w};
        uint32_t hw[2], lw[2];
        #pragma unroll
        for (int j = 0; j < 2; j++) {
            __half h0 = __float2half_rn(xs[2*j]),   h1 = __float2half_rn(xs[2*j+1]);
            __half l0 = __float2half_rn(xs[2*j]   - __half2float(h0));
            __half l1 = __float2half_rn(xs[2*j+1] - __half2float(h1));
            hw[j] = ((uint32_t)__half_as_ushort(h1) << 16) | __half_as_ushort(h0);
            lw[j] = ((uint32_t)__half_as_ushort(l1) << 16) | __half_as_ushort(l0);
        }
        uint32_t* ph = (uint32_t*)&stageH[w][row][c4 * 4];
        uint32_t* pl = (uint32_t*)&stageL[w][row][c4 * 4];
        ph[0] = hw[0]; ph[1] = hw[1];
        pl[0] = lw[0]; pl[1] = lw[1];
    }
    __syncthreads();   // Wo pack (block-wide); own-warp staging also done

    // ---- A-fragments via ldmatrix.x4 (4 k-steps) ----
    const int m = lane >> 3, i8 = lane & 7;
    const int arow = (m & 1) * 8 + i8;
    const int acol = (m >> 1) * 8;
    uint32_t ah[4][4], al[4][4];
    #pragma unroll
    for (int ks = 0; ks < 4; ks++) {
        LDMX4(ah[ks], smem_u32(&stageH[w][arow][ks * 16 + acol]));
        LDMX4(al[ks], smem_u32(&stageL[w][arow][ks * 16 + acol]));
    }

    // ---- 8 e-tiles of n8; 3-pass hi/lo mma; bias in D init ----
    #pragma unroll
    for (int et = 0; et < 8; et++) {
        const float b0v = bos[et * 8 + 2 * t];
        const float b1v = bos[et * 8 + 2 * t + 1];
        float d[4] = {b0v, b1v, b0v, b1v};
        #pragma unroll
        for (int ks = 0; ks < 4; ks++) {
            const int e = et * 8 + g;
            uint32_t bh0 = Wh2[e][ks * 8 + t], bh1 = Wh2[e][ks * 8 + t + 4];
            uint32_t bl0 = Wl2[e][ks * 8 + t], bl1 = Wl2[e][ks * 8 + t + 4];
            MMA_F16(d, ah[ks], bh0, bh1);
            MMA_F16(d, ah[ks], bl0, bl1);
            MMA_F16(d, al[ks], bh0, bh1);
        }
        float2 u;
        u.x = d[0]; u.y = d[1];
        *(float2*)(out + (size_t)(rowbase + g) * EMB + et * 8 + 2 * t) = u;
        u.x = d[2]; u.y = d[3];
        *(float2*)(out + (size_t)(rowbase + g + 8) * EMB + et * 8 + 2 * t) = u;
    }
}

// ---------------------------------------------------------------------------
extern "C" void kernel_launch(void* const* d_in, const int* in_sizes, int n_in,
                              void* d_out, int out_size)
{
    const float* values = (const float*)d_in[0];
    const float* keys   = (const float*)d_in[1];
    const float* query  = (const float*)d_in[2];
    const float* Wv     = (const float*)d_in[3];
    const float* Wk     = (const float*)d_in[4];
    const float* Wq     = (const float*)d_in[5];
    const float* Wo     = (const float*)d_in[6];
    const float* bo     = (const float*)d_in[7];
    float* out = (float*)d_out;

    cudaFuncSetAttribute(attn_kernel,
                         cudaFuncAttributeMaxDynamicSharedMemorySize, DYN_SMEM);

    attn_kernel<<<TT * NH, 256, DYN_SMEM>>>(values, keys, query, Wv, Wk, Wq);
    oproj_kernel<<<(NN * TT) / 128, 256>>>(Wo, bo, out);
}